// round 10
// baseline (speedup 1.0000x reference)
#include <cuda_runtime.h>
#include <cuda_fp16.h>
#include <cstdint>
#include <cstddef>

// ===================== problem constants =====================
constexpr int B_SZ = 8;
constexpr int N_SZ = 2048;
constexpr int D_SZ = 128;

// ===================== GEMM tiling: CTA 64(M) x 128(N) x 32(K) =============
constexpr int SAH = 40;                  // A16 stage row stride (halves)
constexpr int SBH = 40;                  // B stage row stride (halves)
constexpr int A32_B = 64 * 32 * 4;       // 8192 B per fp32 A stage
constexpr int A16_B = 64 * SAH * 2;      // 5120 B per fp16 A stage
constexpr int B_STG = 128 * SBH * 2;     // 10240 B per B stage
constexpr int A32_RING = 4 * A32_B;      // 32768
constexpr int A16_RING = 4 * A16_B;      // 20480
constexpr int B_RING = 4 * B_STG;        // 40960
constexpr int K_ITERS = N_SZ / 32;       // 64
constexpr unsigned DYN_B = A32_RING + A16_RING + B_RING + 256;  // 94464

// h kernel tiling (tf32 path)
constexpr int HS = 36;
constexpr int HSTG = 2 * 128 * HS;
constexpr unsigned DYN_H = 2 * HSTG * 4; // 73728 (also covers 128x136 half transpose buf)
constexpr int SHh = 136;                 // h transpose smem stride (halves)

// scratch: hT[b][e][j] = fp16(leaky_relu(x @ W^T))^T
__device__ __half g_hT[(size_t)B_SZ * D_SZ * N_SZ];

// ===================== helpers =====================
__device__ __forceinline__ uint32_t s2u(const void* p) {
    uint32_t a;
    asm("{ .reg .u64 t; cvta.to.shared.u64 t, %1; cvt.u32.u64 %0, t; }" : "=r"(a) : "l"(p));
    return a;
}
__device__ __forceinline__ void cp16(uint32_t dst, const void* src) {
    asm volatile("cp.async.cg.shared.global [%0], [%1], 16;" :: "r"(dst), "l"(src));
}
__device__ __forceinline__ uint32_t f2tf(float f) {
    uint32_t u;
    asm("cvt.rna.tf32.f32 %0, %1;" : "=r"(u) : "f"(f));
    return u;
}
__device__ __forceinline__ void mma_tf32(float* d, const uint32_t* a, const uint32_t* b) {
    asm volatile(
        "mma.sync.aligned.m16n8k8.row.col.f32.tf32.tf32.f32 "
        "{%0,%1,%2,%3}, {%4,%5,%6,%7}, {%8,%9}, {%0,%1,%2,%3};"
        : "+f"(d[0]), "+f"(d[1]), "+f"(d[2]), "+f"(d[3])
        : "r"(a[0]), "r"(a[1]), "r"(a[2]), "r"(a[3]), "r"(b[0]), "r"(b[1]));
}
__device__ __forceinline__ void mma_f16(float* d, const uint32_t* a, const uint32_t* b) {
    asm volatile(
        "mma.sync.aligned.m16n8k16.row.col.f32.f16.f16.f32 "
        "{%0,%1,%2,%3}, {%4,%5,%6,%7}, {%8,%9}, {%0,%1,%2,%3};"
        : "+f"(d[0]), "+f"(d[1]), "+f"(d[2]), "+f"(d[3])
        : "r"(a[0]), "r"(a[1]), "r"(a[2]), "r"(a[3]), "r"(b[0]), "r"(b[1]));
}
__device__ __forceinline__ __half lrelu_h(float x) {
    float v = x > 0.f ? x : 0.01f * x;
    return __float2half_rn(v);
}

// ===================== kernel 1: hT = fp16(leaky_relu(x @ W^T))^T ===========
__global__ __launch_bounds__(256) void h_kernel(const float* __restrict__ x,
                                                const float* __restrict__ W) {
    extern __shared__ float hdyn[];
    const int tid = threadIdx.x;
    const int b = blockIdx.x >> 4;
    const int j0 = (blockIdx.x & 15) * 128;

    const int wid = tid >> 5;
    const int lane = tid & 31;
    const int g = lane >> 2;
    const int t4 = lane & 3;
    const int wm = wid & 3;
    const int wn = wid >> 2;

    const uint32_t smem_u = s2u(hdyn);
    const float* xg = x + ((size_t)b * N_SZ + j0) * D_SZ;

    auto load_stage = [&](int stage, int kt) {
        const uint32_t xbase = smem_u + stage * HSTG * 4;
        const uint32_t wbase = xbase + 128 * HS * 4;
#pragma unroll
        for (int i = 0; i < 4; i++) {
            int c = tid + i * 256;
            int r = c >> 3, d4 = (c & 7) * 4;
            cp16(xbase + (r * HS + d4) * 4, xg + (size_t)r * D_SZ + kt * 32 + d4);
            cp16(wbase + (r * HS + d4) * 4, W + (size_t)r * D_SZ + kt * 32 + d4);
        }
    };

    float acc[2][8][4];
#pragma unroll
    for (int mt = 0; mt < 2; mt++)
#pragma unroll
        for (int nt = 0; nt < 8; nt++)
#pragma unroll
            for (int q = 0; q < 4; q++) acc[mt][nt][q] = 0.f;

    load_stage(0, 0);
    asm volatile("cp.async.commit_group;" ::: "memory");

    for (int kt = 0; kt < 4; kt++) {
        asm volatile("cp.async.wait_group 0;" ::: "memory");
        __syncthreads();
        if (kt + 1 < 4) {
            load_stage((kt + 1) & 1, kt + 1);
            asm volatile("cp.async.commit_group;" ::: "memory");
        }
        const float* xs = hdyn + (kt & 1) * HSTG;
        const float* ws = xs + 128 * HS;

#pragma unroll
        for (int ks = 0; ks < 4; ks++) {
            uint32_t af[2][4], bf[8][2];
#pragma unroll
            for (int mt = 0; mt < 2; mt++) {
                int r0 = wm * 32 + mt * 16 + g;
                af[mt][0] = f2tf(xs[r0 * HS + ks * 8 + t4]);
                af[mt][1] = f2tf(xs[(r0 + 8) * HS + ks * 8 + t4]);
                af[mt][2] = f2tf(xs[r0 * HS + ks * 8 + t4 + 4]);
                af[mt][3] = f2tf(xs[(r0 + 8) * HS + ks * 8 + t4 + 4]);
            }
#pragma unroll
            for (int nt = 0; nt < 8; nt++) {
                int c0 = wn * 64 + nt * 8 + g;
                bf[nt][0] = f2tf(ws[c0 * HS + ks * 8 + t4]);
                bf[nt][1] = f2tf(ws[c0 * HS + ks * 8 + t4 + 4]);
            }
#pragma unroll
            for (int mt = 0; mt < 2; mt++)
#pragma unroll
                for (int nt = 0; nt < 8; nt++)
                    mma_tf32(acc[mt][nt], af[mt], bf[nt]);
        }
        __syncthreads();
    }

    // ---- transpose through smem, store fp16 hT[e][j] coalesced ----
    __half* hsm = reinterpret_cast<__half*>(hdyn);
#pragma unroll
    for (int mt = 0; mt < 2; mt++)
#pragma unroll
        for (int nt = 0; nt < 8; nt++) {
            int r = wm * 32 + mt * 16 + g;
            int c = wn * 64 + nt * 8 + t4 * 2;
            hsm[c * SHh + r]           = lrelu_h(acc[mt][nt][0]);
            hsm[(c + 1) * SHh + r]     = lrelu_h(acc[mt][nt][1]);
            hsm[c * SHh + r + 8]       = lrelu_h(acc[mt][nt][2]);
            hsm[(c + 1) * SHh + r + 8] = lrelu_h(acc[mt][nt][3]);
        }
    __syncthreads();

    const int e = tid >> 1;
    const int jh = (tid & 1) * 64;
    uint4* dst = reinterpret_cast<uint4*>(g_hT + ((size_t)b * D_SZ + e) * N_SZ + j0 + jh);
    const uint4* src = reinterpret_cast<const uint4*>(hsm + e * SHh + jh);
#pragma unroll
    for (int q = 0; q < 8; q++) dst[q] = src[q];
}

// ===================== kernel 2: fused normalize + An @ h (fp16 MMA) ========
// out[b,i,e] = ( sum_j A[b,i,j] h[b,j,e] + (1 - A[b,i,i]) h[b,i,e] ) / d_i
// d_i = rowsum(A[b,i,:]) - A[b,i,i] + 1
// A path: cp.async fp32 (4-deep) -> convert pass (LDS+cvt+STS, 2 iters ahead)
__global__ __launch_bounds__(256, 2) void gcn_gemm_kernel(const float* __restrict__ A,
                                                          const __half* __restrict__ hTg,
                                                          float* __restrict__ out) {
    extern __shared__ float dyn[];
    __shared__ float rs_sm[512];
    __shared__ float corr_sm[64];
    __shared__ float dinv_sm[64];

    const int tid = threadIdx.x;
    const int b = blockIdx.x >> 5;
    const int gi0 = (blockIdx.x & 31) * 64;

    const int wid = tid >> 5;
    const int lane = tid & 31;
    const int g = lane >> 2;
    const int t4 = lane & 3;
    const int wm = wid & 1;      // 2 row slices of 32
    const int wn = wid >> 1;     // 4 col slices of 32

    const float* Ag = A + (size_t)b * N_SZ * N_SZ;
    const __half* hTb = hTg + (size_t)b * D_SZ * N_SZ;

    // align dynamic smem base to 128B
    const uint32_t raw = s2u(dyn);
    const uint32_t base_u = (raw + 127u) & ~127u;
    char* dbase = reinterpret_cast<char*>(dyn) + (base_u - raw);

    const int r_lo = tid >> 3;           // 0..31 (also handles r_lo+32)
    const int kc = (tid & 7) * 4;        // k offset within 32
    float rs0 = 0.f, rs1 = 0.f;

    // A fp32 tile t -> ring stage t&3 via cp.async
    auto cpA = [&](int t) {
        const uint32_t ab = base_u + (t & 3) * A32_B;
        const float* p = Ag + (size_t)(gi0 + r_lo) * N_SZ + t * 32 + kc;
        cp16(ab + (r_lo * 32 + kc) * 4, p);
        cp16(ab + ((r_lo + 32) * 32 + kc) * 4, p + (size_t)32 * N_SZ);
    };
    // B tile t -> ring stage t&3 via cp.async
    auto cpB = [&](int t) {
        const uint32_t bbase = base_u + A32_RING + A16_RING + (t & 3) * B_STG;
#pragma unroll
        for (int i = 0; i < 2; i++) {
            int c2 = tid + i * 256;
            int e = c2 >> 2, ch = c2 & 3;
            cp16(bbase + e * (SBH * 2) + ch * 16,
                 hTb + (size_t)e * N_SZ + t * 32 + ch * 8);
        }
    };
    // convert A32 tile t -> A16 stage t&3 (+ rowsum; each element counted once)
    auto convert = [&](int t) {
        const float* a32 = reinterpret_cast<const float*>(dbase + (t & 3) * A32_B);
        float4 v0 = *reinterpret_cast<const float4*>(a32 + r_lo * 32 + kc);
        float4 v1 = *reinterpret_cast<const float4*>(a32 + (r_lo + 32) * 32 + kc);
        __half2* ah = reinterpret_cast<__half2*>(dbase + A32_RING + (t & 3) * A16_B);
        int i0 = r_lo * (SAH / 2) + (kc >> 1);
        ah[i0]     = __floats2half2_rn(v0.x, v0.y);
        ah[i0 + 1] = __floats2half2_rn(v0.z, v0.w);
        int i1 = (r_lo + 32) * (SAH / 2) + (kc >> 1);
        ah[i1]     = __floats2half2_rn(v1.x, v1.y);
        ah[i1 + 1] = __floats2half2_rn(v1.z, v1.w);
        rs0 += (v0.x + v0.y) + (v0.z + v0.w);
        rs1 += (v1.x + v1.y) + (v1.z + v1.w);
    };

    float acc[2][4][4];
#pragma unroll
    for (int mt = 0; mt < 2; mt++)
#pragma unroll
        for (int nt = 0; nt < 4; nt++)
#pragma unroll
            for (int q = 0; q < 4; q++) acc[mt][nt][q] = 0.f;

    // ---- prologue (race-free): A4 moved AFTER the converts ----
    // g0{A0,A1,A2}, g1{B0,A3}, g2{B1}, [wait g0, convert 0,1], g3{B2,A4}
    cpA(0); cpA(1); cpA(2);
    asm volatile("cp.async.commit_group;" ::: "memory");   // g0
    cpB(0); cpA(3);
    asm volatile("cp.async.commit_group;" ::: "memory");   // g1
    cpB(1);
    asm volatile("cp.async.commit_group;" ::: "memory");   // g2
    asm volatile("cp.async.wait_group 2;" ::: "memory");   // g0 done: A32 tiles 0..2
    __syncthreads();
    convert(0);
    convert(1);
    cpB(2); cpA(4);                                        // slot 0 write AFTER convert(0) read
    asm volatile("cp.async.commit_group;" ::: "memory");   // g3

    // steady state, iter kt: wait guarantees g(kt+1) = {B(kt), A32(kt+2)}
#pragma unroll 2
    for (int kt = 0; kt < K_ITERS; kt++) {
        asm volatile("cp.async.wait_group 2;" ::: "memory");  // B(kt), A32(kt+2) resident
        __syncthreads();                                       // visible to all; rings rotate

        if (kt + 3 < K_ITERS) cpB(kt + 3);
        if (kt + 5 < K_ITERS) cpA(kt + 5);
        asm volatile("cp.async.commit_group;" ::: "memory");   // g(kt+4) (possibly empty)

        if (kt + 2 < K_ITERS) convert(kt + 2);                 // fills A16 2 iters ahead

        const uint32_t* Ast = reinterpret_cast<const uint32_t*>(
            dbase + A32_RING + (kt & 3) * A16_B);
        const uint32_t* Bst = reinterpret_cast<const uint32_t*>(
            dbase + A32_RING + A16_RING + (kt & 3) * B_STG);

#pragma unroll
        for (int ks = 0; ks < 2; ks++) {
            const int ko = ks * 8;
            uint32_t af[2][4], bf[4][2];
#pragma unroll
            for (int mt = 0; mt < 2; mt++) {
                int r0 = wm * 32 + mt * 16 + g;
                af[mt][0] = Ast[r0 * 20 + ko + t4];
                af[mt][1] = Ast[(r0 + 8) * 20 + ko + t4];
                af[mt][2] = Ast[r0 * 20 + ko + t4 + 4];
                af[mt][3] = Ast[(r0 + 8) * 20 + ko + t4 + 4];
            }
#pragma unroll
            for (int nt = 0; nt < 4; nt++) {
                int c0 = wn * 32 + nt * 8 + g;
                bf[nt][0] = Bst[c0 * 20 + ko + t4];
                bf[nt][1] = Bst[c0 * 20 + ko + t4 + 4];
            }
#pragma unroll
            for (int mt = 0; mt < 2; mt++)
#pragma unroll
                for (int nt = 0; nt < 4; nt++)
                    mma_f16(acc[mt][nt], af[mt], bf[nt]);
        }
    }

    // ---- reductions & epilogue ----
    rs_sm[tid] = rs0;
    rs_sm[256 + tid] = rs1;
    __syncthreads();                    // also: all compute done, rings dead

    if (tid < 64) {
        const float* srcp = (tid < 32) ? (rs_sm + tid * 8) : (rs_sm + 256 + (tid - 32) * 8);
        float d = ((srcp[0] + srcp[1]) + (srcp[2] + srcp[3])) +
                  ((srcp[4] + srcp[5]) + (srcp[6] + srcp[7]));
        float aii = Ag[(size_t)(gi0 + tid) * (N_SZ + 1)];
        float c = 1.0f - aii;           // mask true: A>=0, rows strictly positive
        corr_sm[tid] = c;
        dinv_sm[tid] = 1.0f / (d + c);
    }

    float* o_sm = reinterpret_cast<float*>(dbase);            // [64][132] f32
    float* hf = reinterpret_cast<float*>(dbase) + 64 * 132;   // [128][65] f32
#pragma unroll
    for (int mt = 0; mt < 2; mt++)
#pragma unroll
        for (int nt = 0; nt < 4; nt++) {
            int r = wm * 32 + mt * 16 + g;
            int c = wn * 32 + nt * 8 + t4 * 2;
            o_sm[r * 132 + c]           = acc[mt][nt][0];
            o_sm[r * 132 + c + 1]       = acc[mt][nt][1];
            o_sm[(r + 8) * 132 + c]     = acc[mt][nt][2];
            o_sm[(r + 8) * 132 + c + 1] = acc[mt][nt][3];
        }

    // load hT[:, gi0..gi0+64) tile -> float smem (for diag correction)
    {
        const int e = tid >> 1;
        const int part = tid & 1;
        const uint4* src = reinterpret_cast<const uint4*>(
            hTb + (size_t)e * N_SZ + gi0 + part * 32);
#pragma unroll
        for (int q = 0; q < 4; q++) {
            uint4 v = src[q];
            uint32_t w[4] = {v.x, v.y, v.z, v.w};
#pragma unroll
            for (int u = 0; u < 4; u++) {
                float2 f = __half22float2(*reinterpret_cast<__half2*>(&w[u]));
                hf[e * 65 + part * 32 + q * 8 + u * 2]     = f.x;
                hf[e * 65 + part * 32 + q * 8 + u * 2 + 1] = f.y;
            }
        }
    }
    __syncthreads();

    float* ob = out + ((size_t)b * N_SZ + gi0) * D_SZ;
#pragma unroll 8
    for (int i = tid; i < 64 * 128; i += 256) {
        int r = i >> 7, e = i & 127;
        ob[i] = (o_sm[r * 132 + e] + corr_sm[r] * hf[e * 65 + r]) * dinv_sm[r];
    }
}

// ===================== host =====================
extern "C" void kernel_launch(void* const* d_in, const int* in_sizes, int n_in,
                              void* d_out, int out_size) {
    const float* x = (const float*)d_in[0];
    const float* A = (const float*)d_in[1];
    const float* W = (const float*)d_in[2];
    float* out = (float*)d_out;

    void* hT_ptr = nullptr;
    cudaGetSymbolAddress(&hT_ptr, g_hT);

    cudaFuncSetAttribute(h_kernel, cudaFuncAttributeMaxDynamicSharedMemorySize, DYN_H);
    h_kernel<<<B_SZ * (N_SZ / 128), 256, DYN_H>>>(x, W);

    cudaFuncSetAttribute(gcn_gemm_kernel, cudaFuncAttributeMaxDynamicSharedMemorySize, DYN_B);
    gcn_gemm_kernel<<<B_SZ * (N_SZ / 64), 256, DYN_B>>>(A, (const __half*)hT_ptr, out);
    (void)in_sizes; (void)n_in; (void)out_size;
}